// round 2
// baseline (speedup 1.0000x reference)
#include <cuda_runtime.h>

#define NB 32
#define C  512
#define K  64
#define P  3136
#define CK (C*K)   // 32768

// Scratch (device globals; no allocation allowed in kernel_launch)
__device__ float g_a[(size_t)NB * K * P];   // softmax probs (N,K,P) ~25.7 MB
__device__ float g_wT[C * K];               // conv_w transposed (C,K)
__device__ float g_asum[NB * K];            // sum_p a
__device__ float g_rowsq[NB * C];           // per-(n,c) post-intra-norm sumsq

// ---------------------------------------------------------------- prep: w^T
__global__ void k_prep(const float* __restrict__ w) {
    int t = blockIdx.x * blockDim.x + threadIdx.x;
    if (t < C * K) {
        int c = t >> 6, k = t & 63;
        g_wT[t] = w[k * C + c];   // wT[c][k] = w[k][c]
    }
}

// ------------------------------------------- logits GEMM + softmax over K
// grid (49, 32): block handles 64 pixels of one image. Tile: K=64 x TP=64, inner C.
__global__ __launch_bounds__(256) void k_logits_softmax(
    const float* __restrict__ x, const float* __restrict__ bias)
{
    const int n  = blockIdx.y;
    const int p0 = blockIdx.x * 64;
    __shared__ float sW[16][64];
    __shared__ float sX[16][64];
    __shared__ float sL[64][65];

    const int tid = threadIdx.x;
    const int tx  = tid & 15;   // pixel group
    const int ty  = tid >> 4;   // cluster group

    float acc[4][4];
    #pragma unroll
    for (int i = 0; i < 4; i++)
        #pragma unroll
        for (int j = 0; j < 4; j++) acc[i][j] = 0.f;

    const float* xn = x + (size_t)n * C * P;
    float* sWf = &sW[0][0];

    for (int c0 = 0; c0 < C; c0 += 16) {
        #pragma unroll
        for (int r = 0; r < 4; r++) {
            int idx = tid + r * 256;
            sWf[idx] = g_wT[c0 * 64 + idx];               // coalesced
            int cc = idx >> 6, p = idx & 63;
            sX[cc][p] = xn[(size_t)(c0 + cc) * P + p0 + p]; // coalesced
        }
        __syncthreads();
        #pragma unroll
        for (int cc = 0; cc < 16; cc++) {
            float wv[4], xv[4];
            #pragma unroll
            for (int i = 0; i < 4; i++) wv[i] = sW[cc][ty + 16 * i];
            #pragma unroll
            for (int j = 0; j < 4; j++) xv[j] = sX[cc][tx + 16 * j];
            #pragma unroll
            for (int i = 0; i < 4; i++)
                #pragma unroll
                for (int j = 0; j < 4; j++)
                    acc[i][j] = fmaf(wv[i], xv[j], acc[i][j]);
        }
        __syncthreads();
    }

    // logits(+bias) -> smem
    #pragma unroll
    for (int i = 0; i < 4; i++) {
        float bv = bias[ty + 16 * i];
        #pragma unroll
        for (int j = 0; j < 4; j++)
            sL[ty + 16 * i][tx + 16 * j] = acc[i][j] + bv;
    }
    __syncthreads();

    // softmax over K=64 per pixel; 64 threads, one pixel each
    if (tid < 64) {
        const int p = tid;
        float m = -1e30f;
        #pragma unroll 8
        for (int k = 0; k < 64; k++) m = fmaxf(m, sL[k][p]);
        float s = 0.f;
        #pragma unroll 8
        for (int k = 0; k < 64; k++) {
            float e = __expf(sL[k][p] - m);
            sL[k][p] = e;
            s += e;
        }
        float inv = 1.f / s;
        float* ga = g_a + (size_t)n * K * P + p0 + p;
        #pragma unroll 8
        for (int k = 0; k < 64; k++) ga[(size_t)k * P] = sL[k][p] * inv;
    }
}

// ---------------------------------------------------- asum[n,k] = sum_p a
__global__ __launch_bounds__(256) void k_asum() {
    const int b = blockIdx.x;            // n*64 + k
    const float* row = g_a + (size_t)b * P;
    float s = 0.f;
    for (int i = threadIdx.x; i < P; i += 256) s += row[i];
    __shared__ float red[256];
    red[threadIdx.x] = s;
    __syncthreads();
    for (int o = 128; o > 0; o >>= 1) {
        if (threadIdx.x < o) red[threadIdx.x] += red[threadIdx.x + o];
        __syncthreads();
    }
    if (threadIdx.x == 0) g_asum[b] = red[0];
}

// ----------------- vlad[n,c,k] = sum_p x[n,c,p]*a[n,k,p] - cent[c*K+k]*asum
// grid (4, 32): block computes 128(c) x 64(k), inner P.
__global__ __launch_bounds__(256) void k_vlad(
    const float* __restrict__ x, const float* __restrict__ cent,
    float* __restrict__ out)
{
    const int n  = blockIdx.y;
    const int c0 = blockIdx.x * 128;
    __shared__ float sX[128][33];
    __shared__ float sA[64][33];

    const int tid = threadIdx.x;
    const int tx  = tid & 15;   // k group (k = tx + 16j)
    const int ty  = tid >> 4;   // c group (c = c0 + ty + 16i)

    float acc[8][4];
    #pragma unroll
    for (int i = 0; i < 8; i++)
        #pragma unroll
        for (int j = 0; j < 4; j++) acc[i][j] = 0.f;

    const float* xn = x   + (size_t)n * C * P + (size_t)c0 * P;
    const float* an = g_a + (size_t)n * K * P;

    for (int p0 = 0; p0 < P; p0 += 32) {
        #pragma unroll
        for (int r = 0; r < 16; r++) {
            int idx = tid + r * 256;
            int c = idx >> 5, p = idx & 31;
            sX[c][p] = xn[(size_t)c * P + p0 + p];
        }
        #pragma unroll
        for (int r = 0; r < 8; r++) {
            int idx = tid + r * 256;
            int k = idx >> 5, p = idx & 31;
            sA[k][p] = an[(size_t)k * P + p0 + p];
        }
        __syncthreads();
        #pragma unroll 4
        for (int pp = 0; pp < 32; pp++) {
            float av[4], xv[8];
            #pragma unroll
            for (int j = 0; j < 4; j++) av[j] = sA[tx + 16 * j][pp];
            #pragma unroll
            for (int i = 0; i < 8; i++) xv[i] = sX[ty + 16 * i][pp];
            #pragma unroll
            for (int i = 0; i < 8; i++)
                #pragma unroll
                for (int j = 0; j < 4; j++)
                    acc[i][j] = fmaf(xv[i], av[j], acc[i][j]);
        }
        __syncthreads();
    }

    #pragma unroll
    for (int j = 0; j < 4; j++) {
        const int k = tx + 16 * j;
        const float as = g_asum[n * 64 + k];
        #pragma unroll
        for (int i = 0; i < 8; i++) {
            const int c = c0 + ty + 16 * i;
            out[(size_t)n * CK + c * 64 + k] = acc[i][j] - cent[c * 64 + k] * as;
        }
    }
}

// ------------------------------------------ intra-norm over k per (n,c)
__global__ __launch_bounds__(64) void k_intra(float* __restrict__ out) {
    const int b = blockIdx.x;          // n*512 + c
    const int n = b >> 9;
    const int c = b & 511;
    float* v = out + (size_t)n * CK + c * 64;
    const int t = threadIdx.x;
    float val = v[t];
    float sq = val * val;
    #pragma unroll
    for (int o = 16; o > 0; o >>= 1) sq += __shfl_xor_sync(0xffffffffu, sq, o);
    __shared__ float sh[2];
    if ((t & 31) == 0) sh[t >> 5] = sq;
    __syncthreads();
    float total = sh[0] + sh[1];
    float denom = fmaxf(sqrtf(total), 1e-12f);
    v[t] = val / denom;
    if (t == 0) g_rowsq[b] = total / (denom * denom);
}

// ------------------------------------------ global L2-norm per n
__global__ __launch_bounds__(256) void k_final(float* __restrict__ out) {
    const int n = blockIdx.x;
    const int t = threadIdx.x;
    __shared__ float red[256];
    red[t] = g_rowsq[n * 512 + t] + g_rowsq[n * 512 + 256 + t];
    __syncthreads();
    for (int o = 128; o > 0; o >>= 1) {
        if (t < o) red[t] += red[t + o];
        __syncthreads();
    }
    __shared__ float inv;
    if (t == 0) inv = 1.f / fmaxf(sqrtf(red[0]), 1e-12f);
    __syncthreads();
    float* v = out + (size_t)n * CK;
    for (int j = t; j < CK; j += 256) v[j] *= inv;
}

extern "C" void kernel_launch(void* const* d_in, const int* in_sizes, int n_in,
                              void* d_out, int out_size) {
    const float* x    = (const float*)d_in[0];   // (32,512,56,56)
    const float* cent = (const float*)d_in[1];   // (64,512)
    const float* w    = (const float*)d_in[2];   // (64,512)
    const float* b    = (const float*)d_in[3];   // (64,)
    float* out = (float*)d_out;                  // (32, 32768)

    k_prep<<<128, 256>>>(w);
    k_logits_softmax<<<dim3(49, 32), 256>>>(x, b);
    k_asum<<<NB * K, 256>>>();
    k_vlad<<<dim3(4, 32), 256>>>(x, cent, out);
    k_intra<<<NB * C, 64>>>(out);
    k_final<<<NB, 256>>>(out);
}

// round 3
// speedup vs baseline: 2.3389x; 2.3389x over previous
#include <cuda_runtime.h>

#define NB 32
#define C  512
#define K  64
#define P  3136
#define CK (C*K)       // 32768
#define NSPLIT 7
#define PCH (P/NSPLIT) // 448

// Scratch (device globals; no allocation allowed in kernel_launch)
__device__ float g_a[(size_t)NB * K * P];          // softmax probs (N,K,P) ~25.7 MB
__device__ float g_part[(size_t)NSPLIT * NB * CK]; // vlad partials ~29.4 MB
__device__ float g_wT[C * K];                      // conv_w transposed (C,K)
__device__ float g_asum[NB * K];                   // sum_p a
__device__ float g_rowsq[NB * C];                  // per-(n,c) post-intra-norm sumsq

// ---------------------------------------------------------------- prep: w^T
__global__ void k_prep(const float* __restrict__ w) {
    int t = blockIdx.x * blockDim.x + threadIdx.x;
    if (t < C * K) {
        int c = t >> 6, k = t & 63;
        g_wT[t] = w[k * C + c];   // wT[c][k] = w[k][c]
    }
}

// ------------------------------------------- logits GEMM + softmax over K
// grid (25, 32): block handles 128 pixels of one image (last tile: 64 valid).
// Tile: K=64 x 128 pixels, inner C in chunks of 16. Per thread: 8k x 4p.
__global__ __launch_bounds__(256) void k_logits_softmax(
    const float* __restrict__ x, const float* __restrict__ bias)
{
    const int n  = blockIdx.y;
    const int p0 = blockIdx.x * 128;

    __shared__ float pool[64 * 129];          // 33 KB; reused for sL after GEMM
    float* sW = pool;                          // [16][64]
    float* sX = pool + 1024;                   // [16][128]

    const int tid = threadIdx.x;
    const int tx  = tid & 31;    // pixel group: p = tx + 32*j
    const int ky  = tid >> 5;    // cluster group: k = ky + 8*i

    float acc[8][4];
    #pragma unroll
    for (int i = 0; i < 8; i++)
        #pragma unroll
        for (int j = 0; j < 4; j++) acc[i][j] = 0.f;

    const float* xn = x + (size_t)n * C * P;

    for (int c0 = 0; c0 < C; c0 += 16) {
        #pragma unroll
        for (int r = 0; r < 4; r++) {
            int idx = tid + r * 256;
            sW[idx] = g_wT[c0 * 64 + idx];                 // coalesced
        }
        #pragma unroll
        for (int r = 0; r < 8; r++) {
            int idx = tid + r * 256;
            int cc = idx >> 7, p = idx & 127;
            int gp = p0 + p;
            sX[idx] = (gp < P) ? xn[(size_t)(c0 + cc) * P + gp] : 0.f;
        }
        __syncthreads();
        #pragma unroll
        for (int cc = 0; cc < 16; cc++) {
            float wv[8], xv[4];
            #pragma unroll
            for (int i = 0; i < 8; i++) wv[i] = sW[cc * 64 + ky + 8 * i];
            #pragma unroll
            for (int j = 0; j < 4; j++) xv[j] = sX[cc * 128 + tx + 32 * j];
            #pragma unroll
            for (int i = 0; i < 8; i++)
                #pragma unroll
                for (int j = 0; j < 4; j++)
                    acc[i][j] = fmaf(wv[i], xv[j], acc[i][j]);
        }
        __syncthreads();
    }

    // logits(+bias) -> smem (sL[64][129] overlaps sW/sX, dead now)
    #pragma unroll
    for (int i = 0; i < 8; i++) {
        const int kk = ky + 8 * i;
        const float bv = bias[kk];
        #pragma unroll
        for (int j = 0; j < 4; j++)
            pool[kk * 129 + tx + 32 * j] = acc[i][j] + bv;
    }
    __syncthreads();

    // softmax over K=64 per pixel; 128 threads, one pixel each
    if (tid < 128 && p0 + tid < P) {
        const int p = tid;
        float m = -1e30f;
        #pragma unroll 8
        for (int k = 0; k < 64; k++) m = fmaxf(m, pool[k * 129 + p]);
        float s = 0.f;
        #pragma unroll 8
        for (int k = 0; k < 64; k++) {
            float e = __expf(pool[k * 129 + p] - m);
            pool[k * 129 + p] = e;
            s += e;
        }
        float inv = 1.f / s;
        float* ga = g_a + (size_t)n * K * P + p0 + p;
        #pragma unroll 8
        for (int k = 0; k < 64; k++) ga[(size_t)k * P] = pool[k * 129 + p] * inv;
    }
}

// ---------------------------------------------------- asum[n,k] = sum_p a
__global__ __launch_bounds__(256) void k_asum() {
    const int b = blockIdx.x;            // n*64 + k
    const float* row = g_a + (size_t)b * P;
    float s = 0.f;
    for (int i = threadIdx.x; i < P; i += 256) s += row[i];
    __shared__ float red[256];
    red[threadIdx.x] = s;
    __syncthreads();
    for (int o = 128; o > 0; o >>= 1) {
        if (threadIdx.x < o) red[threadIdx.x] += red[threadIdx.x + o];
        __syncthreads();
    }
    if (threadIdx.x == 0) g_asum[b] = red[0];
}

// --------------- vlad partial: part[s,n,c,k] = sum_{p in chunk} x*a
// grid (4, 7, 32): block computes 128(c) x 64(k) over 448 pixels.
__global__ __launch_bounds__(256) void k_vlad_part(const float* __restrict__ x)
{
    const int n  = blockIdx.z;
    const int s  = blockIdx.y;
    const int c0 = blockIdx.x * 128;
    const int pbeg = s * PCH;

    __shared__ float sX[128][33];
    __shared__ float sA[64][33];

    const int tid = threadIdx.x;
    const int tx  = tid & 15;   // k group (k = tx + 16j)
    const int ty  = tid >> 4;   // c group (c = c0 + ty + 16i)

    float acc[8][4];
    #pragma unroll
    for (int i = 0; i < 8; i++)
        #pragma unroll
        for (int j = 0; j < 4; j++) acc[i][j] = 0.f;

    const float* xn = x   + (size_t)n * C * P + (size_t)c0 * P;
    const float* an = g_a + (size_t)n * K * P;

    for (int p0 = pbeg; p0 < pbeg + PCH; p0 += 32) {
        #pragma unroll
        for (int r = 0; r < 16; r++) {
            int idx = tid + r * 256;
            int c = idx >> 5, p = idx & 31;
            sX[c][p] = xn[(size_t)c * P + p0 + p];
        }
        #pragma unroll
        for (int r = 0; r < 8; r++) {
            int idx = tid + r * 256;
            int k = idx >> 5, p = idx & 31;
            sA[k][p] = an[(size_t)k * P + p0 + p];
        }
        __syncthreads();
        #pragma unroll 4
        for (int pp = 0; pp < 32; pp++) {
            float av[4], xv[8];
            #pragma unroll
            for (int j = 0; j < 4; j++) av[j] = sA[tx + 16 * j][pp];
            #pragma unroll
            for (int i = 0; i < 8; i++) xv[i] = sX[ty + 16 * i][pp];
            #pragma unroll
            for (int i = 0; i < 8; i++)
                #pragma unroll
                for (int j = 0; j < 4; j++)
                    acc[i][j] = fmaf(xv[i], av[j], acc[i][j]);
        }
        __syncthreads();
    }

    float* gp = g_part + ((size_t)s * NB + n) * CK;
    #pragma unroll
    for (int j = 0; j < 4; j++) {
        const int k = tx + 16 * j;
        #pragma unroll
        for (int i = 0; i < 8; i++) {
            const int c = c0 + ty + 16 * i;
            gp[c * 64 + k] = acc[i][j];
        }
    }
}

// --------------- combine partials + centroid correction + intra-norm
__global__ __launch_bounds__(64) void k_combine_intra(
    const float* __restrict__ cent, float* __restrict__ out)
{
    const int b = blockIdx.x;          // n*512 + c
    const int n = b >> 9;
    const int c = b & 511;
    const int t = threadIdx.x;         // k

    float val = 0.f;
    #pragma unroll
    for (int s = 0; s < NSPLIT; s++)
        val += g_part[((size_t)s * NB + n) * CK + c * 64 + t];
    val -= cent[c * 64 + t] * g_asum[n * 64 + t];

    float sq = val * val;
    #pragma unroll
    for (int o = 16; o > 0; o >>= 1) sq += __shfl_xor_sync(0xffffffffu, sq, o);
    __shared__ float sh[2];
    if ((t & 31) == 0) sh[t >> 5] = sq;
    __syncthreads();
    float total = sh[0] + sh[1];
    float denom = fmaxf(sqrtf(total), 1e-12f);
    out[(size_t)n * CK + c * 64 + t] = val / denom;
    if (t == 0) g_rowsq[b] = total / (denom * denom);
}

// ------------------------------------------ global L2-norm per n
__global__ __launch_bounds__(256) void k_final(float* __restrict__ out) {
    const int n = blockIdx.x;
    const int t = threadIdx.x;
    __shared__ float red[256];
    red[t] = g_rowsq[n * 512 + t] + g_rowsq[n * 512 + 256 + t];
    __syncthreads();
    for (int o = 128; o > 0; o >>= 1) {
        if (t < o) red[t] += red[t + o];
        __syncthreads();
    }
    __shared__ float inv;
    if (t == 0) inv = 1.f / fmaxf(sqrtf(red[0]), 1e-12f);
    __syncthreads();
    float* v = out + (size_t)n * CK;
    for (int j = t; j < CK; j += 256) v[j] *= inv;
}

extern "C" void kernel_launch(void* const* d_in, const int* in_sizes, int n_in,
                              void* d_out, int out_size) {
    const float* x    = (const float*)d_in[0];   // (32,512,56,56)
    const float* cent = (const float*)d_in[1];   // (64,512)
    const float* w    = (const float*)d_in[2];   // (64,512)
    const float* b    = (const float*)d_in[3];   // (64,)
    float* out = (float*)d_out;                  // (32, 32768)

    k_prep<<<128, 256>>>(w);
    k_logits_softmax<<<dim3(25, 32), 256>>>(x, b);
    k_asum<<<NB * K, 256>>>();
    k_vlad_part<<<dim3(4, NSPLIT, NB), 256>>>(x);
    k_combine_intra<<<NB * C, 64>>>(cent, out);
    k_final<<<NB, 256>>>(out);
}

// round 6
// speedup vs baseline: 3.7615x; 1.6083x over previous
#include <cuda_runtime.h>
#include <cstdint>

#define NB 32
#define C  512
#define K  64
#define P  3136
#define CK (C*K)        // 32768
#define PSPLIT 2
#define PCH (P/PSPLIT)  // 1568

// Scratch (device globals; allocation forbidden elsewhere)
__device__ __align__(256) float g_a[(size_t)NB * K * P];          // softmax probs ~25.7MB
__device__ __align__(256) float g_part[(size_t)PSPLIT * NB * CK]; // vlad partials
__device__ __align__(256) float g_asum[NB * K];
__device__ __align__(256) float g_rowsq[NB * C];

__device__ __forceinline__ float tf32_rn(float x) {
    uint32_t u; asm("cvt.rna.tf32.f32 %0, %1;" : "=r"(u) : "f"(x));
    return __uint_as_float(u);
}
__device__ __forceinline__ void mma8(float acc[4], const uint32_t a[4],
                                     uint32_t b0, uint32_t b1) {
    asm volatile(
        "mma.sync.aligned.m16n8k8.row.col.f32.tf32.tf32.f32 "
        "{%0,%1,%2,%3}, {%4,%5,%6,%7}, {%8,%9}, {%0,%1,%2,%3};"
        : "+f"(acc[0]), "+f"(acc[1]), "+f"(acc[2]), "+f"(acc[3])
        : "r"(a[0]), "r"(a[1]), "r"(a[2]), "r"(a[3]), "r"(b0), "r"(b1));
}
__device__ __forceinline__ uint32_t fu(float x) { return __float_as_uint(x); }

// Shared compute: CTA tile 128(M) x 64(N), chunk K=32. Warps 4(M) x 2(N).
// A in sAh/sAl (row-major [M][32], stride SA), B in sBh/sBl ([N][32], stride 36).
template <int SA>
__device__ __forceinline__ void compute_chunk(
    const float* sAh, const float* sAl, const float* sBh, const float* sBl,
    float acc[2][4][4], int wm, int wn, int g, int t)
{
    #pragma unroll
    for (int kk = 0; kk < 4; kk++) {
        const int kc = kk * 8;
        uint32_t ah[2][4], al[2][4];
        #pragma unroll
        for (int mt = 0; mt < 2; mt++) {
            const int r0 = (wm * 32 + mt * 16 + g) * SA + kc + t;
            const int r1 = r0 + 8 * SA;
            ah[mt][0] = fu(sAh[r0]);     ah[mt][1] = fu(sAh[r1]);
            ah[mt][2] = fu(sAh[r0 + 4]); ah[mt][3] = fu(sAh[r1 + 4]);
            al[mt][0] = fu(sAl[r0]);     al[mt][1] = fu(sAl[r1]);
            al[mt][2] = fu(sAl[r0 + 4]); al[mt][3] = fu(sAl[r1 + 4]);
        }
        #pragma unroll
        for (int nt = 0; nt < 4; nt++) {
            const int nb = (wn * 32 + nt * 8 + g) * 36 + kc + t;
            const uint32_t bh0 = fu(sBh[nb]), bh1 = fu(sBh[nb + 4]);
            const uint32_t bl0 = fu(sBl[nb]), bl1 = fu(sBl[nb + 4]);
            #pragma unroll
            for (int mt = 0; mt < 2; mt++) {
                mma8(acc[mt][nt], ah[mt], bh0, bh1);
                mma8(acc[mt][nt], ah[mt], bl0, bl1);
                mma8(acc[mt][nt], al[mt], bh0, bh1);
            }
        }
    }
}

// ===================== GEMM1: logits + softmax =====================
// grid (25, 32). M=128 pixels x N=64 clusters; contraction C=512, 16 chunks of 32.
// smem pool (floats): sAh@0 (128*37), sAl@4736, sBh@9472 (64*36), sBl@11776,
// bias@14080; sL (128*65) overlays sAh/sAl in epilogue. Total 14144 floats.
#define G1_SMEM (14144 * 4)
__global__ __launch_bounds__(256, 2) void k_logits_tc(
    const float* __restrict__ x, const float* __restrict__ w,
    const float* __restrict__ bias)
{
    extern __shared__ float pool[];
    float* sAh = pool;
    float* sAl = pool + 4736;
    float* sBh = pool + 9472;
    float* sBl = pool + 11776;
    float* sBias = pool + 14080;
    float* sL = pool;                 // epilogue overlay [128][65]

    const int tid = threadIdx.x, lane = tid & 31, wid = tid >> 5;
    const int g = lane >> 2, t = lane & 3;
    const int wm = wid & 3, wn = wid >> 2;
    const int n = blockIdx.y, p0 = blockIdx.x * 128;

    if (tid < 64) sBias[tid] = bias[tid];

    const float* xn = x + (size_t)n * C * P;
    const int pl = tid & 127;            // pixel column this thread stages
    const bool pok = (p0 + pl) < P;
    const int cb = tid >> 7;             // 0/1

    float acc[2][4][4];
    #pragma unroll
    for (int mt = 0; mt < 2; mt++)
        #pragma unroll
        for (int nt = 0; nt < 4; nt++)
            #pragma unroll
            for (int q = 0; q < 4; q++) acc[mt][nt][q] = 0.f;

    float xv[16], wv[8];
    // preload chunk 0
    #pragma unroll
    for (int r = 0; r < 16; r++)
        xv[r] = pok ? xn[(size_t)(cb + 2 * r) * P + p0 + pl] : 0.f;
    #pragma unroll
    for (int r = 0; r < 8; r++)
        wv[r] = w[(size_t)((tid >> 5) + 8 * r) * C + (tid & 31)];

    for (int i = 0; i < 16; i++) {
        if (i) __syncthreads();
        // stage + split
        #pragma unroll
        for (int r = 0; r < 16; r++) {
            const int cc = cb + 2 * r;
            const float v = xv[r], h = tf32_rn(v);
            sAh[pl * 37 + cc] = h;
            sAl[pl * 37 + cc] = v - h;
        }
        #pragma unroll
        for (int r = 0; r < 8; r++) {
            const int k = (tid >> 5) + 8 * r, c = tid & 31;
            const float v = wv[r], h = tf32_rn(v);
            sBh[k * 36 + c] = h;
            sBl[k * 36 + c] = v - h;
        }
        __syncthreads();
        if (i + 1 < 16) {
            const int c0 = (i + 1) * 32;
            #pragma unroll
            for (int r = 0; r < 16; r++)
                xv[r] = pok ? xn[(size_t)(c0 + cb + 2 * r) * P + p0 + pl] : 0.f;
            #pragma unroll
            for (int r = 0; r < 8; r++)
                wv[r] = w[(size_t)((tid >> 5) + 8 * r) * C + c0 + (tid & 31)];
        }
        compute_chunk<37>(sAh, sAl, sBh, sBl, acc, wm, wn, g, t);
    }

    // epilogue: logits -> sL, softmax over k per pixel
    __syncthreads();
    #pragma unroll
    for (int mt = 0; mt < 2; mt++) {
        const int pr = wm * 32 + mt * 16 + g;
        #pragma unroll
        for (int nt = 0; nt < 4; nt++) {
            const int k0 = wn * 32 + nt * 8 + 2 * t;
            sL[pr * 65 + k0]           = acc[mt][nt][0] + sBias[k0];
            sL[pr * 65 + k0 + 1]       = acc[mt][nt][1] + sBias[k0 + 1];
            sL[(pr + 8) * 65 + k0]     = acc[mt][nt][2] + sBias[k0];
            sL[(pr + 8) * 65 + k0 + 1] = acc[mt][nt][3] + sBias[k0 + 1];
        }
    }
    __syncthreads();
    if (tid < 128 && p0 + tid < P) {
        const float* row = sL + tid * 65;
        float v[64], m = -1e30f;
        #pragma unroll
        for (int k = 0; k < 64; k++) { v[k] = row[k]; m = fmaxf(m, v[k]); }
        float s = 0.f;
        #pragma unroll
        for (int k = 0; k < 64; k++) { v[k] = __expf(v[k] - m); s += v[k]; }
        const float inv = 1.f / s;
        float* ga = g_a + (size_t)n * K * P + p0 + tid;
        #pragma unroll
        for (int k = 0; k < 64; k++) ga[(size_t)k * P] = v[k] * inv;
    }
}

// ===================== GEMM2: vlad partials =====================
// grid (4, PSPLIT, 32). M=128 c x N=64 k; contraction 1568 p, 49 chunks of 32.
// smem (floats): sXh@0 (128*36), sXl@4608, sBh@9216 (64*36), sBl@11520. 13824 floats.
#define G2_SMEM (13824 * 4)
__global__ __launch_bounds__(256, 2) void k_vlad_tc(const float* __restrict__ x)
{
    extern __shared__ float pool2[];
    float* sXh = pool2;
    float* sXl = pool2 + 4608;
    float* sBh = pool2 + 9216;
    float* sBl = pool2 + 11520;

    const int tid = threadIdx.x, lane = tid & 31, wid = tid >> 5;
    const int g = lane >> 2, t = lane & 3;
    const int wm = wid & 3, wn = wid >> 2;
    const int n = blockIdx.z, sp = blockIdx.y, c0 = blockIdx.x * 128;

    const float* xn = x + ((size_t)n * C + c0) * P;
    const float* an = g_a + (size_t)n * K * P;
    const int pb0 = sp * PCH;
    const int pl = tid & 31;

    float acc[2][4][4];
    #pragma unroll
    for (int mt = 0; mt < 2; mt++)
        #pragma unroll
        for (int nt = 0; nt < 4; nt++)
            #pragma unroll
            for (int q = 0; q < 4; q++) acc[mt][nt][q] = 0.f;

    float xv[16], av[8];
    #pragma unroll
    for (int r = 0; r < 16; r++)
        xv[r] = xn[(size_t)((tid >> 5) + 8 * r) * P + pb0 + pl];
    #pragma unroll
    for (int r = 0; r < 8; r++)
        av[r] = an[(size_t)((tid >> 5) + 8 * r) * P + pb0 + pl];

    for (int i = 0; i < 49; i++) {
        if (i) __syncthreads();
        #pragma unroll
        for (int r = 0; r < 16; r++) {
            const int row = (tid >> 5) + 8 * r;
            const float v = xv[r], h = tf32_rn(v);
            sXh[row * 36 + pl] = h;
            sXl[row * 36 + pl] = v - h;
        }
        #pragma unroll
        for (int r = 0; r < 8; r++) {
            const int k = (tid >> 5) + 8 * r;
            const float v = av[r], h = tf32_rn(v);
            sBh[k * 36 + pl] = h;
            sBl[k * 36 + pl] = v - h;
        }
        __syncthreads();
        if (i + 1 < 49) {
            const int pb = pb0 + (i + 1) * 32;
            #pragma unroll
            for (int r = 0; r < 16; r++)
                xv[r] = xn[(size_t)((tid >> 5) + 8 * r) * P + pb + pl];
            #pragma unroll
            for (int r = 0; r < 8; r++)
                av[r] = an[(size_t)((tid >> 5) + 8 * r) * P + pb + pl];
        }
        compute_chunk<36>(sXh, sXl, sBh, sBl, acc, wm, wn, g, t);
    }

    float* gp = g_part + ((size_t)sp * NB + n) * CK;
    #pragma unroll
    for (int mt = 0; mt < 2; mt++) {
        const int cr = c0 + wm * 32 + mt * 16 + g;
        #pragma unroll
        for (int nt = 0; nt < 4; nt++) {
            const int k0 = wn * 32 + nt * 8 + 2 * t;
            *(float2*)(gp + (size_t)cr * 64 + k0) =
                make_float2(acc[mt][nt][0], acc[mt][nt][1]);
            *(float2*)(gp + (size_t)(cr + 8) * 64 + k0) =
                make_float2(acc[mt][nt][2], acc[mt][nt][3]);
        }
    }
}

// ---------------------------------------------------- asum[n,k] = sum_p a
__global__ __launch_bounds__(256) void k_asum() {
    const int b = blockIdx.x;
    const float* row = g_a + (size_t)b * P;
    float s = 0.f;
    for (int i = threadIdx.x; i < P; i += 256) s += row[i];
    __shared__ float red[256];
    red[threadIdx.x] = s;
    __syncthreads();
    for (int o = 128; o > 0; o >>= 1) {
        if (threadIdx.x < o) red[threadIdx.x] += red[threadIdx.x + o];
        __syncthreads();
    }
    if (threadIdx.x == 0) g_asum[b] = red[0];
}

// --------------- combine partials + centroid correction + intra-norm
__global__ __launch_bounds__(64) void k_combine_intra(
    const float* __restrict__ cent, float* __restrict__ out)
{
    const int b = blockIdx.x;          // n*512 + c
    const int n = b >> 9;
    const int c = b & 511;
    const int t = threadIdx.x;         // k

    float val = g_part[(size_t)n * CK + c * 64 + t]
              + g_part[((size_t)NB + n) * CK + c * 64 + t];
    val -= cent[c * 64 + t] * g_asum[n * 64 + t];

    float sq = val * val;
    #pragma unroll
    for (int o = 16; o > 0; o >>= 1) sq += __shfl_xor_sync(0xffffffffu, sq, o);
    __shared__ float sh[2];
    if ((t & 31) == 0) sh[t >> 5] = sq;
    __syncthreads();
    float total = sh[0] + sh[1];
    float denom = fmaxf(sqrtf(total), 1e-12f);
    out[(size_t)n * CK + c * 64 + t] = val / denom;
    if (t == 0) g_rowsq[b] = total / (denom * denom);
}

// ------------------------------------------ global L2-norm per n
__global__ __launch_bounds__(256) void k_final(float* __restrict__ out) {
    const int n = blockIdx.x;
    const int t = threadIdx.x;
    __shared__ float red[256];
    red[t] = g_rowsq[n * 512 + t] + g_rowsq[n * 512 + 256 + t];
    __syncthreads();
    for (int o = 128; o > 0; o >>= 1) {
        if (t < o) red[t] += red[t + o];
        __syncthreads();
    }
    __shared__ float inv;
    if (t == 0) inv = 1.f / fmaxf(sqrtf(red[0]), 1e-12f);
    __syncthreads();
    float* v = out + (size_t)n * CK;
    for (int j = t; j < CK; j += 256) v[j] *= inv;
}

extern "C" void kernel_launch(void* const* d_in, const int* in_sizes, int n_in,
                              void* d_out, int out_size) {
    const float* x    = (const float*)d_in[0];   // (32,512,56,56)
    const float* cent = (const float*)d_in[1];   // (64,512)
    const float* w    = (const float*)d_in[2];   // (64,512)
    const float* b    = (const float*)d_in[3];   // (64,)
    float* out = (float*)d_out;                  // (32, 32768)

    cudaFuncSetAttribute(k_logits_tc, cudaFuncAttributeMaxDynamicSharedMemorySize, G1_SMEM);
    cudaFuncSetAttribute(k_vlad_tc,   cudaFuncAttributeMaxDynamicSharedMemorySize, G2_SMEM);

    k_logits_tc<<<dim3(25, 32), 256, G1_SMEM>>>(x, w, b);
    k_asum<<<NB * K, 256>>>();
    k_vlad_tc<<<dim3(4, PSPLIT, NB), 256, G2_SMEM>>>(x);
    k_combine_intra<<<NB * C, 64>>>(cent, out);
    k_final<<<NB, 256>>>(out);
}